// round 5
// baseline (speedup 1.0000x reference)
#include <cuda_runtime.h>
#include <math.h>
#include <cstdint>

#define BB 4
#define NN 8192

// ---------------- device scratch ----------------
__device__ float g_tproj[BB*256];
__device__ float g_pbest[4*BB*NN];
__device__ int   g_pidx [4*BB*NN];
__device__ float g_nearest[BB*NN*3];
// weights: [N][K/2] u32, each u32 = 2 bf16 (low half = even k), hi/lo split parts
__device__ uint32_t g_w1h[4*256*128], g_w1l[4*256*128];
__device__ uint32_t g_w2h[4*256*128], g_w2l[4*256*128];
__device__ uint32_t g_owh[128*128],   g_owl[128*128];

// ================= helpers =================
__device__ __forceinline__ uint32_t smem_to_u32(const void* p) {
    uint32_t a;
    asm("{ .reg .u64 t; cvta.to.shared.u64 t, %1; cvt.u32.u64 %0, t; }" : "=r"(a) : "l"(p));
    return a;
}
__device__ __forceinline__ void cp_async16(uint32_t d, const void* s) {
    asm volatile("cp.async.ca.shared.global [%0], [%1], 16;" :: "r"(d), "l"(s) : "memory");
}
#define CP_COMMIT() asm volatile("cp.async.commit_group;" ::: "memory")
template<int N> __device__ __forceinline__ void cp_wait() {
    asm volatile("cp.async.wait_group %0;" :: "n"(N) : "memory");
}
// split two floats into packed bf16 hi-part and bf16 lo-part (low half = first arg)
__device__ __forceinline__ void split2(float x0, float x1, uint32_t& hi, uint32_t& lo) {
    uint32_t h;
    asm("cvt.rn.bf16x2.f32 %0, %1, %2;" : "=r"(h) : "f"(x1), "f"(x0));
    float h0 = __uint_as_float(h << 16);
    float h1 = __uint_as_float(h & 0xFFFF0000u);
    float l0 = x0 - h0, l1 = x1 - h1;
    uint32_t l;
    asm("cvt.rn.bf16x2.f32 %0, %1, %2;" : "=r"(l) : "f"(l1), "f"(l0));
    hi = h; lo = l;
}
__device__ __forceinline__ float bfl(uint32_t u) { return __uint_as_float(u << 16); }
__device__ __forceinline__ float bfh(uint32_t u) { return __uint_as_float(u & 0xFFFF0000u); }

__device__ __forceinline__ void mmabf(float c[4], const uint32_t a[4], const uint32_t b[2]) {
    asm volatile(
        "mma.sync.aligned.m16n8k16.row.col.f32.bf16.bf16.f32 "
        "{%0,%1,%2,%3}, {%4,%5,%6,%7}, {%8,%9}, {%0,%1,%2,%3};"
        : "+f"(c[0]), "+f"(c[1]), "+f"(c[2]), "+f"(c[3])
        : "r"(a[0]), "r"(a[1]), "r"(a[2]), "r"(a[3]), "r"(b[0]), "r"(b[1]));
}
__device__ __forceinline__ float silu(float x) { return x / (1.0f + __expf(-x)); }

// smem u32/float offsets
#define O_XH    0        // 64 x 132 u32 (x hi, 2 bf16/u32 along K)
#define O_XL    8448
#define O_HH    16896    // h hi (also reused as fp32 y1 [64][132] for head)
#define O_HL    25344
#define O_WB    33792    // 2 x (256 rows x 36 u32): [16 hi | 16 lo | 4 pad]
#define O_B1    52224
#define O_GA    52480
#define O_BE    52736
#define O_B2    52992
#define O_CV    53248
#define O_INW   53504    // 1536
#define O_OB1   55040    // 128
#define O_W2    55168    // 384
#define O_OB2   55552    // 4
#define O_SRS   55556    // 512 (64 rows x 8 wn)
#define O_SRQ   56068    // 512
#define O_MU    56580    // 64
#define O_RS    56644    // 64
#define SMEM_F  56708
#define SMEM_BYTES (SMEM_F*4)

// ============ weight transpose + bf16 hi/lo split + pack ============
__global__ void transpose_kernel(const float* __restrict__ ly_w1,
                                 const float* __restrict__ ly_w2,
                                 const float* __restrict__ out_w1)
{
    __shared__ float ts[32][33];   // ts[k_local][n_local]
    int m = blockIdx.x >> 6, tile = blockIdx.x & 63;
    const float* src; uint32_t *dh, *dl; int N = 256;
    if (m < 4)      { src = ly_w1 + m*65536;     dh = g_w1h + m*32768; dl = g_w1l + m*32768; }
    else if (m < 8) { src = ly_w2 + (m-4)*65536; dh = g_w2h + (m-4)*32768; dl = g_w2l + (m-4)*32768; }
    else            { src = out_w1;              dh = g_owh; dl = g_owl; N = 128; }
    int tn = (tile & 7) * 32, tk = (tile >> 3) * 32;
    if (tn >= N) return;
    int lx = threadIdx.x & 31, ly = threadIdx.x >> 5;
    #pragma unroll
    for (int i = 0; i < 32; i += 8) ts[ly+i][lx] = src[(tk+ly+i)*N + tn + lx];
    __syncthreads();
    int kk = lx & 15; bool ishi = lx < 16;
    #pragma unroll
    for (int i = 0; i < 32; i += 8) {
        int nl = ly + i;
        float x0 = ts[2*kk][nl], x1 = ts[2*kk+1][nl];
        uint32_t h, l; split2(x0, x1, h, l);
        int idx = (tn + nl)*128 + (tk >> 1) + kk;
        if (ishi) dh[idx] = h; else dl[idx] = l;
    }
}

// ============ time embedding ============
__global__ void temb_kernel(const int* __restrict__ timesteps,
                            const float* __restrict__ te_w1, const float* __restrict__ te_b1,
                            const float* __restrict__ te_w2, const float* __restrict__ te_b2,
                            const float* __restrict__ tp_w,  const float* __restrict__ tp_b)
{
    __shared__ float emb[128], h1[512], h2[512];
    int b = blockIdx.x, t = threadIdx.x;
    if (t < 64) {
        float fr = expf((float)t * (-logf(10000.0f) / 63.0f));
        float an = (float)timesteps[b] * fr;
        emb[t] = sinf(an); emb[t+64] = cosf(an);
    }
    __syncthreads();
    { float a = te_b1[t];
      #pragma unroll 4
      for (int k = 0; k < 128; k++) a = fmaf(emb[k], te_w1[k*512+t], a);
      h1[t] = a / (1.0f + expf(-a)); }
    __syncthreads();
    { float a = te_b2[t];
      #pragma unroll 4
      for (int k = 0; k < 512; k++) a = fmaf(h1[k], te_w2[k*512+t], a);
      h2[t] = a; }
    __syncthreads();
    if (t < 256) {
        float a = tp_b[t];
        #pragma unroll 4
        for (int k = 0; k < 512; k++) a = fmaf(h2[k], tp_w[k*256+t], a);
        g_tproj[b*256+t] = a;
    }
}

// ============ nearest neighbor (known-good) ============
#define TSZ 2048
__global__ void nn_kernel(const float* __restrict__ noisy, const float* __restrict__ target)
{
    __shared__ float4 ts[TSZ];
    int b = blockIdx.x >> 8, chunk = (blockIdx.x >> 2) & 63, slice = blockIdx.x & 3;
    int t = threadIdx.x;
    const float4* tg4 = (const float4*)(target + ((size_t)b*NN + (size_t)slice*TSZ) * 3);
    for (int p4 = t; p4 < TSZ/4; p4 += 128) {
        float4 v0 = tg4[3*p4], v1 = tg4[3*p4+1], v2 = tg4[3*p4+2];
        ts[4*p4+0] = make_float4(v0.x, v0.y, v0.z, 0.5f*(v0.x*v0.x + v0.y*v0.y + v0.z*v0.z));
        ts[4*p4+1] = make_float4(v0.w, v1.x, v1.y, 0.5f*(v0.w*v0.w + v1.x*v1.x + v1.y*v1.y));
        ts[4*p4+2] = make_float4(v1.z, v1.w, v2.x, 0.5f*(v1.z*v1.z + v1.w*v1.w + v2.x*v2.x));
        ts[4*p4+3] = make_float4(v2.y, v2.z, v2.w, 0.5f*(v2.y*v2.y + v2.z*v2.z + v2.w*v2.w));
    }
    __syncthreads();
    int p = chunk*128 + t;
    const float* q = noisy + ((size_t)b*NN + p) * 3;
    float qx = -q[0], qy = -q[1], qz = -q[2];
    float best = INFINITY; int bidx = 0;
    #pragma unroll 8
    for (int j = 0; j < TSZ; j++) {
        float4 v = ts[j];
        float e = fmaf(qx, v.x, v.w); e = fmaf(qy, v.y, e); e = fmaf(qz, v.z, e);
        if (e < best) { best = e; bidx = j; }
    }
    int pi = b*NN + p;
    g_pbest[slice*(BB*NN) + pi] = best;
    g_pidx [slice*(BB*NN) + pi] = slice*TSZ + bidx;
}
__global__ void nn_reduce_kernel(const float* __restrict__ target)
{
    int pi = blockIdx.x * 256 + threadIdx.x;
    float best = g_pbest[pi]; int bidx = g_pidx[pi];
    #pragma unroll
    for (int s = 1; s < 4; s++) {
        float v = g_pbest[s*(BB*NN) + pi];
        if (v < best) { best = v; bidx = g_pidx[s*(BB*NN) + pi]; }
    }
    int b = pi >> 13;
    const float* tc = target + ((size_t)b*NN + bidx) * 3;
    g_nearest[pi*3+0] = tc[0]; g_nearest[pi*3+1] = tc[1]; g_nearest[pi*3+2] = tc[2];
}

// ============ fused bf16x3 mma MLP ============
__device__ __forceinline__ void loadW(uint32_t* smu, int buf,
                                      const uint32_t* __restrict__ gh,
                                      const uint32_t* __restrict__ gl,
                                      int kc, int nRows, int t)
{
    uint32_t base = smem_to_u32(smu + O_WB + buf*9216);
    int tot = nRows*8;
    #pragma unroll
    for (int i = t; i < tot; i += 512) {
        int n = i >> 3, j = i & 7;
        if (j < 4) cp_async16(base + (uint32_t)((n*36 + j*4)*4),      gh + n*128 + kc*16 + j*4);
        else       cp_async16(base + (uint32_t)((n*36 + 16 + (j-4)*4)*4), gl + n*128 + kc*16 + (j-4)*4);
    }
}

template<int NT>   // NT n8-tiles per warp: 4 => N=256 (8 n-warps), 2 => N=128
__device__ __forceinline__ void gemm_bf3(uint32_t* smu, int AH, int AL,
                                         const uint32_t* __restrict__ gh,
                                         const uint32_t* __restrict__ gl,
                                         int nRows, float c[2][NT][4],
                                         int t, int wm, int wn, int g, int tt)
{
    loadW(smu, 0, gh, gl, 0, nRows, t); CP_COMMIT();
    #pragma unroll 1
    for (int kc = 0; kc < 8; kc++) {
        __syncthreads();                       // prior buffer consumers done
        if (kc < 7) { loadW(smu, (kc+1)&1, gh, gl, kc+1, nRows, t); CP_COMMIT(); cp_wait<1>(); }
        else cp_wait<0>();
        __syncthreads();                       // tile kc visible
        int WBo = O_WB + (kc&1)*9216;
        #pragma unroll
        for (int ks = 0; ks < 2; ks++) {
            int cb = kc*16 + ks*8;
            uint32_t ah[2][4], al[2][4];
            #pragma unroll
            for (int mi = 0; mi < 2; mi++) {
                int r = wm*32 + mi*16 + g;
                int i0 = r*132 + cb + tt;
                int i1 = (r+8)*132 + cb + tt;
                ah[mi][0]=smu[AH+i0]; ah[mi][1]=smu[AH+i1]; ah[mi][2]=smu[AH+i0+4]; ah[mi][3]=smu[AH+i1+4];
                al[mi][0]=smu[AL+i0]; al[mi][1]=smu[AL+i1]; al[mi][2]=smu[AL+i0+4]; al[mi][3]=smu[AL+i1+4];
            }
            uint32_t bh[NT][2], bl[NT][2];
            #pragma unroll
            for (int nt = 0; nt < NT; nt++) {
                int n = wn*(NT*8) + nt*8 + g;
                int ib = WBo + n*36 + ks*8 + tt;
                bh[nt][0]=smu[ib];    bh[nt][1]=smu[ib+4];
                bl[nt][0]=smu[ib+16]; bl[nt][1]=smu[ib+20];
            }
            #pragma unroll
            for (int mi = 0; mi < 2; mi++)
                #pragma unroll
                for (int nt = 0; nt < NT; nt++) {
                    mmabf(c[mi][nt], ah[mi], bh[nt]);   // hi*hi
                    mmabf(c[mi][nt], ah[mi], bl[nt]);   // hi*lo
                    mmabf(c[mi][nt], al[mi], bh[nt]);   // lo*hi
                }
        }
    }
    __syncthreads();
}

__global__ __launch_bounds__(512, 1)
void mlp_mma(const float* __restrict__ noisy,
             const float* __restrict__ in_w,  const float* __restrict__ in_b,
             const float* __restrict__ ly_b1, const float* __restrict__ ly_g,
             const float* __restrict__ ly_be, const float* __restrict__ ly_b2,
             const float* __restrict__ out_b1, const float* __restrict__ out_w2,
             const float* __restrict__ out_b2, float* __restrict__ out)
{
    extern __shared__ float sm[];
    uint32_t* smu = (uint32_t*)sm;
    int t = threadIdx.x, lane = t & 31, w = t >> 5;
    int wm = w & 1, wn = w >> 1;           // warp grid 2(M) x 8(N)
    int g = lane >> 2, tt = lane & 3;
    int b = blockIdx.x >> 7, row0 = (blockIdx.x & 127) << 6;

    // ---- stage constants ----
    if (t < 256) sm[O_CV + t] = in_b[t] + g_tproj[b*256 + t];
    for (int i = t; i < 1536; i += 512) sm[O_INW + i] = in_w[i];
    if (t < 128) sm[O_OB1 + t] = out_b1[t];
    if (t < 384) sm[O_W2 + t] = out_w2[t];
    if (t < 3)   sm[O_OB2 + t] = out_b2[t];
    __syncthreads();

    // ---- input build: x = feat @ in_w + (in_b + tproj) -> hi/lo bf16 pairs ----
    {
        int row = t >> 3, q = t & 7;
        int gp = b*NN + row0 + row;
        float f[6];
        f[0]=noisy[gp*3]; f[1]=noisy[gp*3+1]; f[2]=noisy[gp*3+2];
        f[3]=g_nearest[gp*3]; f[4]=g_nearest[gp*3+1]; f[5]=g_nearest[gp*3+2];
        #pragma unroll
        for (int c4 = 0; c4 < 8; c4++) {
            int col = q*32 + c4*4;
            float4 a = *(const float4*)(sm + O_CV + col);
            #pragma unroll
            for (int k = 0; k < 6; k++) {
                float4 wv = *(const float4*)(sm + O_INW + k*256 + col);
                a.x = fmaf(f[k], wv.x, a.x); a.y = fmaf(f[k], wv.y, a.y);
                a.z = fmaf(f[k], wv.z, a.z); a.w = fmaf(f[k], wv.w, a.w);
            }
            uint32_t h0,l0,h1,l1;
            split2(a.x, a.y, h0, l0);
            split2(a.z, a.w, h1, l1);
            int idx = row*132 + (col >> 1);
            smu[O_XH + idx] = h0; smu[O_XH + idx + 1] = h1;
            smu[O_XL + idx] = l0; smu[O_XL + idx + 1] = l1;
        }
    }
    __syncthreads();

    // ---- 4 residual layers ----
    #pragma unroll 1
    for (int lay = 0; lay < 4; lay++) {
        if (t < 256) {
            sm[O_B1 + t] = ly_b1[lay*256 + t]; sm[O_GA + t] = ly_g [lay*256 + t];
            sm[O_BE + t] = ly_be[lay*256 + t]; sm[O_B2 + t] = ly_b2[lay*256 + t];
        }
        __syncthreads();

        // GEMM1: D = x @ W1
        float c1[2][4][4];
        #pragma unroll
        for (int mi = 0; mi < 2; mi++)
            #pragma unroll
            for (int nt = 0; nt < 4; nt++)
                { c1[mi][nt][0]=0.f; c1[mi][nt][1]=0.f; c1[mi][nt][2]=0.f; c1[mi][nt][3]=0.f; }
        gemm_bf3<4>(smu, O_XH, O_XL, g_w1h + lay*32768, g_w1l + lay*32768, 256, c1, t, wm, wn, g, tt);

        // epilogue1: +b1, LN stats
        float S[2][2] = {{0,0},{0,0}}, Q[2][2] = {{0,0},{0,0}};
        #pragma unroll
        for (int mi = 0; mi < 2; mi++)
            #pragma unroll
            for (int nt = 0; nt < 4; nt++) {
                int bc = wn*32 + nt*8 + 2*tt;
                float b0 = sm[O_B1 + bc], b1v = sm[O_B1 + bc + 1];
                float v0 = c1[mi][nt][0] + b0, v1 = c1[mi][nt][1] + b1v;
                float v2 = c1[mi][nt][2] + b0, v3 = c1[mi][nt][3] + b1v;
                c1[mi][nt][0]=v0; c1[mi][nt][1]=v1; c1[mi][nt][2]=v2; c1[mi][nt][3]=v3;
                S[mi][0] += v0 + v1; Q[mi][0] = fmaf(v0,v0,fmaf(v1,v1,Q[mi][0]));
                S[mi][1] += v2 + v3; Q[mi][1] = fmaf(v2,v2,fmaf(v3,v3,Q[mi][1]));
            }
        #pragma unroll
        for (int mi = 0; mi < 2; mi++)
            #pragma unroll
            for (int h = 0; h < 2; h++) {
                float s = S[mi][h], q = Q[mi][h];
                s += __shfl_xor_sync(0xffffffffu, s, 1); s += __shfl_xor_sync(0xffffffffu, s, 2);
                q += __shfl_xor_sync(0xffffffffu, q, 1); q += __shfl_xor_sync(0xffffffffu, q, 2);
                if (tt == 0) {
                    int row = wm*32 + mi*16 + h*8 + g;
                    sm[O_SRS + row*8 + wn] = s;
                    sm[O_SRQ + row*8 + wn] = q;
                }
            }
        __syncthreads();
        if (t < 64) {
            float s = 0.f, q = 0.f;
            #pragma unroll
            for (int i = 0; i < 8; i++) { s += sm[O_SRS + t*8 + i]; q += sm[O_SRQ + t*8 + i]; }
            float mu = s * (1.f/256.f);
            float rs = rsqrtf(fmaf(-mu, mu, q * (1.f/256.f)) + 1e-5f);
            sm[O_MU + t] = mu; sm[O_RS + t] = rs;
        }
        __syncthreads();
        // LN + SiLU -> h hi/lo bf16 pairs
        #pragma unroll
        for (int mi = 0; mi < 2; mi++)
            #pragma unroll
            for (int h = 0; h < 2; h++) {
                int row = wm*32 + mi*16 + h*8 + g;
                float mu = sm[O_MU + row], rs = sm[O_RS + row];
                #pragma unroll
                for (int nt = 0; nt < 4; nt++) {
                    int bc = wn*32 + nt*8 + 2*tt;
                    float v0 = c1[mi][nt][2*h], v1 = c1[mi][nt][2*h + 1];
                    float h0 = silu(fmaf((v0 - mu)*rs, sm[O_GA + bc],     sm[O_BE + bc]));
                    float h1 = silu(fmaf((v1 - mu)*rs, sm[O_GA + bc + 1], sm[O_BE + bc + 1]));
                    uint32_t hh, ll; split2(h0, h1, hh, ll);
                    int idx = row*132 + (bc >> 1);
                    smu[O_HH + idx] = hh; smu[O_HL + idx] = ll;
                }
            }
        __syncthreads();

        // GEMM2: D = h @ W2
        float c2[2][4][4];
        #pragma unroll
        for (int mi = 0; mi < 2; mi++)
            #pragma unroll
            for (int nt = 0; nt < 4; nt++)
                { c2[mi][nt][0]=0.f; c2[mi][nt][1]=0.f; c2[mi][nt][2]=0.f; c2[mi][nt][3]=0.f; }
        gemm_bf3<4>(smu, O_HH, O_HL, g_w2h + lay*32768, g_w2l + lay*32768, 256, c2, t, wm, wn, g, tt);

        // epilogue2: x = x + D + b2 (recombine hi/lo, resplit)
        #pragma unroll
        for (int mi = 0; mi < 2; mi++)
            #pragma unroll
            for (int h = 0; h < 2; h++) {
                int row = wm*32 + mi*16 + h*8 + g;
                #pragma unroll
                for (int nt = 0; nt < 4; nt++) {
                    int bc = wn*32 + nt*8 + 2*tt;
                    int idx = row*132 + (bc >> 1);
                    uint32_t xh = smu[O_XH + idx], xl = smu[O_XL + idx];
                    float x0 = bfl(xh) + bfl(xl) + c2[mi][nt][2*h]     + sm[O_B2 + bc];
                    float x1 = bfh(xh) + bfh(xl) + c2[mi][nt][2*h + 1] + sm[O_B2 + bc + 1];
                    uint32_t nh, nl; split2(x0, x1, nh, nl);
                    smu[O_XH + idx] = nh; smu[O_XL + idx] = nl;
                }
            }
        __syncthreads();
    }

    // ---- head GEMM: D = x @ out_w1 (N=128) ----
    float ch[2][2][4];
    #pragma unroll
    for (int mi = 0; mi < 2; mi++)
        #pragma unroll
        for (int nt = 0; nt < 2; nt++)
            { ch[mi][nt][0]=0.f; ch[mi][nt][1]=0.f; ch[mi][nt][2]=0.f; ch[mi][nt][3]=0.f; }
    gemm_bf3<2>(smu, O_XH, O_XL, g_owh, g_owl, 128, ch, t, wm, wn, g, tt);

    // y1 = silu(D + b1) -> plain fp32 [64][132] in O_HH region
    #pragma unroll
    for (int mi = 0; mi < 2; mi++)
        #pragma unroll
        for (int h = 0; h < 2; h++) {
            int row = wm*32 + mi*16 + h*8 + g;
            #pragma unroll
            for (int nt = 0; nt < 2; nt++) {
                int bc = wn*16 + nt*8 + 2*tt;
                sm[O_HH + row*132 + bc]     = silu(ch[mi][nt][2*h]     + sm[O_OB1 + bc]);
                sm[O_HH + row*132 + bc + 1] = silu(ch[mi][nt][2*h + 1] + sm[O_OB1 + bc + 1]);
            }
        }
    __syncthreads();

    // ---- final: score = y1 @ out_w2 + out_b2 (128 -> 3, fp32) ----
    if (t < 192) {
        int rr = t / 3, p = t - rr*3;
        float a = sm[O_OB2 + p];
        const float* y = sm + O_HH + rr*132;
        #pragma unroll 8
        for (int k = 0; k < 128; k++) a = fmaf(y[k], sm[O_W2 + k*3 + p], a);
        out[(size_t)((b*NN + row0 + rr)*3 + p)] = a;
    }
}

// =====================================================================
extern "C" void kernel_launch(void* const* d_in, const int* in_sizes, int n_in,
                              void* d_out, int out_size)
{
    const float* noisy  = (const float*)d_in[0];
    const float* target = (const float*)d_in[1];
    const int*   tsteps = (const int*)  d_in[2];
    const float* te_w1  = (const float*)d_in[3];
    const float* te_b1  = (const float*)d_in[4];
    const float* te_w2  = (const float*)d_in[5];
    const float* te_b2  = (const float*)d_in[6];
    const float* tp_w   = (const float*)d_in[7];
    const float* tp_b   = (const float*)d_in[8];
    const float* in_w   = (const float*)d_in[9];
    const float* in_b   = (const float*)d_in[10];
    const float* ly_w1  = (const float*)d_in[11];
    const float* ly_b1  = (const float*)d_in[12];
    const float* ly_g   = (const float*)d_in[13];
    const float* ly_be  = (const float*)d_in[14];
    const float* ly_w2  = (const float*)d_in[15];
    const float* ly_b2  = (const float*)d_in[16];
    const float* out_w1 = (const float*)d_in[17];
    const float* out_b1 = (const float*)d_in[18];
    const float* out_w2 = (const float*)d_in[19];
    const float* out_b2 = (const float*)d_in[20];
    float* out = (float*)d_out;

    cudaFuncSetAttribute(mlp_mma, cudaFuncAttributeMaxDynamicSharedMemorySize, SMEM_BYTES);

    transpose_kernel<<<576, 256>>>(ly_w1, ly_w2, out_w1);
    temb_kernel<<<4, 512>>>(tsteps, te_w1, te_b1, te_w2, te_b2, tp_w, tp_b);
    nn_kernel<<<1024, 128>>>(noisy, target);
    nn_reduce_kernel<<<128, 256>>>(target);
    mlp_mma<<<512, 512, SMEM_BYTES>>>(noisy, in_w, in_b,
                                      ly_b1, ly_g, ly_be, ly_b2,
                                      out_b1, out_w2, out_b2, out);
}